// round 6
// baseline (speedup 1.0000x reference)
#include <cuda_runtime.h>

// PerturbedTopK: x (64,196) f32, noise (64,500,196) f32.
// out[b,k,d] = mean_n [ sorted(top49_idx(x_b + 0.05*noise_bn))[k] == d ].
//
// One warp processes TWO rows (A,B) concurrently for ILP: the two threshold
// searches interleave (14 FSET + 2 REDUX per iter), halving exposed
// REDUX/branch latency per row and amortizing loop control.
// Stepping: Newton with fixed Gaussian-density slope every iter (open-interval
// bracket test, midpoint only on escape), plus exact terminal steps when
// |c-49|<=3 (pivot := min(selected) or pred(max(unselected)) via REDUX
// min/max on monotonic keys). Exact termination requires count==49; cap 24
// then exact MSB-radix fallback with index-order tie-break.

#define BATCH 64
#define NSAMP 500
#define DIM   196
#define TOPK  49
#define SIGMA 0.05f

#define OUTN  (BATCH * TOPK * DIM)
#define FULLM 0xffffffffu
#define NEGBIG (-3.402823466e38f)

__device__ __forceinline__ unsigned f2key(float v) {
    unsigned u = __float_as_uint(v);
    return u ^ ((unsigned)((int)u >> 31) | 0x80000000u);
}
__device__ __forceinline__ float key2f(unsigned k) {
    unsigned u = (k & 0x80000000u) ? (k ^ 0x80000000u) : ~k;
    return __uint_as_float(u);
}
// 0xFFFFFFFF if a > b else 0 (single SASS FSET).
__device__ __forceinline__ unsigned fgt(float a, float b) {
    unsigned r;
    asm("set.gt.u32.f32 %0, %1, %2;" : "=r"(r) : "f"(a), "f"(b));
    return r;
}

// Rank-and-accumulate for a tie-free threshold T (exactly TOPK strictly above).
__device__ __forceinline__ void emit(const float val[7], float T,
                                     float* __restrict__ outb,
                                     int lane, unsigned lt, float invn) {
    int base = 0;
    #pragma unroll
    for (int j = 0; j < 7; j++) {
        const int d = j * 32 + lane;
        const bool s = val[j] > T;
        const unsigned mb = __ballot_sync(FULLM, s);
        if (s) {
            const int rank = base + __popc(mb & lt);
            atomicAdd(outb + rank * DIM + d, invn);
        }
        base += __popc(mb);
    }
}

// Exact MSB radix select + emit, with index-order tie-break (cold path).
__device__ void radix_emit(const float val[7], float* __restrict__ outb,
                           int lane, unsigned lt, float invn) {
    unsigned actm = (6 * 32 + lane < DIM) ? 0x7Fu : 0x3Fu;
    int k = TOPK, matching = DIM, s = 0;
    unsigned P = 0u;
    #pragma unroll 1
    for (int bit = 31; bit >= 0; --bit) {
        const unsigned m = 1u << bit;
        int c = 0;
        #pragma unroll
        for (int j = 0; j < 7; j++)
            c += (((actm >> j) & 1u) && (f2key(val[j]) & m)) ? 1 : 0;
        c = __reduce_add_sync(FULLM, c);
        if (c >= k) {
            P |= m; matching = c;
            #pragma unroll
            for (int j = 0; j < 7; j++)
                if (!(f2key(val[j]) & m)) actm &= ~(1u << j);
        } else {
            k -= c; matching -= c;
            #pragma unroll
            for (int j = 0; j < 7; j++)
                if (f2key(val[j]) & m) actm &= ~(1u << j);
        }
        s = bit;
        if (matching == k) break;
    }
    const unsigned Ph = P >> s;
    int gtb = 0, eqb = 0;
    #pragma unroll
    for (int j = 0; j < 7; j++) {
        const int d = j * 32 + lane;
        const bool gt = (d < DIM) && ((f2key(val[j]) >> s) > Ph);
        const bool eq = ((actm >> j) & 1u) != 0u;
        const unsigned mg = __ballot_sync(FULLM, gt);
        const unsigned me = __ballot_sync(FULLM, eq);
        const int gtp = gtb + __popc(mg & lt);
        const int eqp = eqb + __popc(me & lt);
        if (gt || (eq && eqp < k)) {
            const int rank = gtp + min(eqp, k);
            atomicAdd(outb + rank * DIM + d, invn);
        }
        gtb += __popc(mg);
        eqb += __popc(me);
    }
}

// One search update for a row. All branch conditions are warp-uniform.
__device__ __forceinline__ void step(const float val[7], int c,
                                     float& piv, float& lo, float& hi,
                                     float& T, bool& found) {
    if (found) return;
    if (c == TOPK) { T = piv; found = true; return; }
    const bool g = (c > TOPK);
    lo = g ? piv : lo;
    hi = g ? hi  : piv;
    const int dd = c - TOPK;
    float p;
    if (dd > 0 && dd <= 3) {
        unsigned mk = 0xFFFFFFFFu;                 // min key among selected
        #pragma unroll
        for (int j = 0; j < 7; j++)
            mk = min(mk, (val[j] > piv) ? f2key(val[j]) : 0xFFFFFFFFu);
        mk = __reduce_min_sync(FULLM, mk);
        p = key2f(mk);
    } else if (dd < 0 && dd >= -3) {
        unsigned Mk = 0u;                          // max key among unselected
        #pragma unroll
        for (int j = 0; j < 7; j++)
            Mk = max(Mk, (val[j] > piv) ? 0u : f2key(val[j]));
        Mk = __reduce_max_sync(FULLM, Mk);
        p = key2f(Mk - 1u);                        // key-predecessor
    } else {
        p = fmaf((float)dd, 0.0166667f, piv);      // Newton, slope ~ n*phi(q)
    }
    if (!(p > lo && p < hi)) p = 0.5f * (lo + hi); // bracket escape -> bisect
    piv = p;
}

__global__ __launch_bounds__(256)
void ptopk_kernel(const float* __restrict__ x,
                  const float* __restrict__ noise,
                  float* __restrict__ out) {
    const int warp = threadIdx.x >> 5;
    const int lane = threadIdx.x & 31;
    const int b    = blockIdx.y;
    const int ribA = blockIdx.x * 16 + warp * 2;   // rows in batch
    const int ribB = ribA + 1;
    const bool hasA = (ribA < NSAMP);
    const bool hasB = (ribB < NSAMP);

    const float* __restrict__ xr = x + b * DIM;
    const float* __restrict__ nA = noise + ((size_t)b * NSAMP + ribA) * DIM;
    const float* __restrict__ nB = nA + DIM;
    const unsigned lt = (1u << lane) - 1u;
    const float invn = 1.0f / (float)NSAMP;
    float* __restrict__ outb = out + b * (TOPK * DIM);

    float valA[7], valB[7];
    #pragma unroll
    for (int j = 0; j < 7; j++) {
        const int d = j * 32 + lane;
        const bool v = (d < DIM);
        const float xv = v ? xr[d] : 0.0f;
        valA[j] = (v && hasA) ? fmaf(nA[d], SIGMA, xv) : NEGBIG;
        valB[j] = (v && hasB) ? fmaf(nB[d], SIGMA, xv) : NEGBIG;
    }

    // ---- dual interleaved threshold search ----
    float loA = 0.0f, hiA = 1.5f, pivA = 0.674f, TA = 0.0f;
    float loB = 0.0f, hiB = 1.5f, pivB = 0.674f, TB = 0.0f;
    bool foundA = !hasA, foundB = !hasB;

    #pragma unroll 1
    for (int it = 0; it < 24 && (!foundA || !foundB); ++it) {
        unsigned aA = 0, aB = 0;
        #pragma unroll
        for (int j = 0; j < 7; j++) {
            aA += fgt(valA[j], pivA);              // -1 per hit
            aB += fgt(valB[j], pivB);
        }
        const int cA = -(int)__reduce_add_sync(FULLM, (int)aA);
        const int cB = -(int)__reduce_add_sync(FULLM, (int)aB);
        step(valA, cA, pivA, loA, hiA, TA, foundA);
        step(valB, cB, pivB, loB, hiB, TB, foundB);
    }

    if (hasA) {
        if (foundA) emit(valA, TA, outb, lane, lt, invn);
        else        radix_emit(valA, outb, lane, lt, invn);
    }
    if (hasB) {
        if (foundB) emit(valB, TB, outb, lane, lt, invn);
        else        radix_emit(valB, outb, lane, lt, invn);
    }
}

extern "C" void kernel_launch(void* const* d_in, const int* in_sizes, int n_in,
                              void* d_out, int out_size) {
    const float* x     = (const float*)d_in[0];
    const float* noise = (const float*)d_in[1];
    if (n_in >= 2 && in_sizes[0] > in_sizes[1]) {
        x     = (const float*)d_in[1];
        noise = (const float*)d_in[0];
    }
    float* out = (float*)d_out;

    cudaMemsetAsync(out, 0, (size_t)OUTN * sizeof(float));
    dim3 grid(32, BATCH, 1);   // 32*16 = 512 row slots >= 500 per batch
    ptopk_kernel<<<grid, 256>>>(x, noise, out);
}